// round 7
// baseline (speedup 1.0000x reference)
#include <cuda_runtime.h>
#include <cuda_bf16.h>
#include <cstdint>

#define B_  64
#define D_  128
#define LC  1024
#define LQ  256
#define LDS_ 40      // smem row stride in bf16 elements (conflict-free for ldmatrix)

// ---------------- scratch (static device arrays) ----------------
static __device__ __nv_bfloat16 g_Ehi[(size_t)B_*LC*LQ];  // E hi bf16
static __device__ __nv_bfloat16 g_Elo[(size_t)B_*LC*LQ];  // E lo bf16 (residual)
static __device__ float g_At  [(size_t)B_*D_*LC];    // A^T  [d][l]
static __device__ float g_T   [(size_t)B_*LQ*D_];    // T-hat [m][d] (qm*cinv folded)
static __device__ float g_rinv[B_*LC];
static __device__ float g_qcinv[B_*LQ];
static __device__ float g_cpart[B_*8*LQ];
static __device__ float g_c1[B_*LC];
static __device__ float g_q2[B_*LQ];

// ---------------- helpers ----------------
#define LDSM_X4(r, a) \
    asm volatile("ldmatrix.sync.aligned.m8n8.x4.shared.b16 {%0,%1,%2,%3}, [%4];" \
        : "=r"((r)[0]), "=r"((r)[1]), "=r"((r)[2]), "=r"((r)[3]) : "r"(a))

#define MMA_BF16(c, a, b0, b1) \
    asm volatile("mma.sync.aligned.m16n8k16.row.col.f32.bf16.bf16.f32 " \
        "{%0,%1,%2,%3}, {%4,%5,%6,%7}, {%8,%9}, {%0,%1,%2,%3};" \
        : "+f"((c)[0]), "+f"((c)[1]), "+f"((c)[2]), "+f"((c)[3]) \
        : "r"((a)[0]), "r"((a)[1]), "r"((a)[2]), "r"((a)[3]), "r"(b0), "r"(b1))

__device__ __forceinline__ uint32_t smem_u32(const void* p) {
    uint32_t a;
    asm("{ .reg .u64 t; cvta.to.shared.u64 t, %1; cvt.u32.u64 %0, t; }" : "=r"(a) : "l"(p));
    return a;
}

__device__ __forceinline__ uint32_t pack_bf2(float x, float y) {
    __nv_bfloat162 t(__float2bfloat16(x), __float2bfloat16(y));
    return *reinterpret_cast<uint32_t*>(&t);
}

__device__ __forceinline__ void cvt4(const float4& x, uint2& uh, uint2& ul) {
    __nv_bfloat16 hx = __float2bfloat16(x.x), hy = __float2bfloat16(x.y);
    __nv_bfloat16 hz = __float2bfloat16(x.z), hw = __float2bfloat16(x.w);
    __nv_bfloat162 h01(hx, hy), h23(hz, hw);
    __nv_bfloat162 l01(__float2bfloat16(x.x - __bfloat162float(hx)),
                       __float2bfloat16(x.y - __bfloat162float(hy)));
    __nv_bfloat162 l23(__float2bfloat16(x.z - __bfloat162float(hz)),
                       __float2bfloat16(x.w - __bfloat162float(hw)));
    uh.x = *reinterpret_cast<uint32_t*>(&h01); uh.y = *reinterpret_cast<uint32_t*>(&h23);
    ul.x = *reinterpret_cast<uint32_t*>(&l01); ul.y = *reinterpret_cast<uint32_t*>(&l23);
}

// ---------------- operand loaders ----------------
// logical: element (mn, klocal) -> smem[mn*LDS_ + klocal]
// FMT 0: fp32, K-fast   src[mn*ld + k]       (+opt per-k scale)
// FMT 1: fp32, K-slow   src[k*ld + mn]       (+opt per-k scale)
// FMT 2: bf16-pair, K-fast
// FMT 3: bf16-pair, K-slow
template<int FMT, bool KS>
__device__ __forceinline__ void ldg_op(const float* __restrict__ f32,
                                       const __nv_bfloat16* __restrict__ bhi,
                                       const __nv_bfloat16* __restrict__ blo,
                                       int ld, int mn0, int kk,
                                       const float* __restrict__ ks,
                                       int tid, uint2 (&uh)[4], uint2 (&ul)[4]) {
#pragma unroll
    for (int i = 0; i < 4; i++) {
        int v = i * 256 + tid;
        if constexpr (FMT == 0) {
            int row = v >> 3, c4 = v & 7;
            float4 x = *reinterpret_cast<const float4*>(f32 + (size_t)(mn0 + row) * ld + kk + c4 * 4);
            if constexpr (KS) {
                float4 s = *reinterpret_cast<const float4*>(ks + kk + c4 * 4);
                x.x *= s.x; x.y *= s.y; x.z *= s.z; x.w *= s.w;
            }
            cvt4(x, uh[i], ul[i]);
        } else if constexpr (FMT == 1) {
            int mn = v & 127, krb = v >> 7;
            const float* p = f32 + (size_t)(kk + krb * 4) * ld + mn0 + mn;
            float4 x;
            x.x = p[0]; x.y = p[ld]; x.z = p[2 * (size_t)ld]; x.w = p[3 * (size_t)ld];
            if constexpr (KS) {
                const float* s = ks + kk + krb * 4;
                x.x *= s[0]; x.y *= s[1]; x.z *= s[2]; x.w *= s[3];
            }
            cvt4(x, uh[i], ul[i]);
        } else if constexpr (FMT == 2) {
            int row = v >> 3, c4 = v & 7;
            size_t off = (size_t)(mn0 + row) * ld + kk + c4 * 4;
            uh[i] = *reinterpret_cast<const uint2*>(bhi + off);
            ul[i] = *reinterpret_cast<const uint2*>(blo + off);
        } else {
            int mn = v & 127, krb = v >> 7;
            size_t off = (size_t)(kk + krb * 4) * ld + mn0 + mn;
            const unsigned short* ph = reinterpret_cast<const unsigned short*>(bhi);
            const unsigned short* pl = reinterpret_cast<const unsigned short*>(blo);
            uint32_t h0 = ph[off], h1 = ph[off + ld];
            uint32_t h2 = ph[off + 2 * (size_t)ld], h3 = ph[off + 3 * (size_t)ld];
            uh[i].x = h0 | (h1 << 16); uh[i].y = h2 | (h3 << 16);
            uint32_t l0 = pl[off], l1 = pl[off + ld];
            uint32_t l2 = pl[off + 2 * (size_t)ld], l3 = pl[off + 3 * (size_t)ld];
            ul[i].x = l0 | (l1 << 16); ul[i].y = l2 | (l3 << 16);
        }
    }
}

template<int FMT>
__device__ __forceinline__ void sts_op(uint2 (&uh)[4], uint2 (&ul)[4],
                                       __nv_bfloat16* smh, __nv_bfloat16* sml, int tid) {
#pragma unroll
    for (int i = 0; i < 4; i++) {
        int v = i * 256 + tid;
        int off;
        if constexpr (FMT == 0 || FMT == 2) { int row = v >> 3, c4 = v & 7; off = row * LDS_ + c4 * 4; }
        else                                { int mn = v & 127, krb = v >> 7; off = mn * LDS_ + krb * 4; }
        *reinterpret_cast<uint2*>(smh + off) = uh[i];
        *reinterpret_cast<uint2*>(sml + off) = ul[i];
    }
}

// ---------------- bf16 3-pass tensor GEMM: Out(m,n) = sum_k A(m,k)*B(n,k) ----------------
// EPI 1: E = exp(acc + c1[row] + q2[col]) -> bf16 hi/lo pair
// EPI 2: acc * scale[row] -> fp32
// EPI 3: acc * scale[col] -> fp32
// EPI 4: bv = acc * scale[col]; load C(row,col), At(row,col); write 4 output channels
template<int AF, int BF, bool KSA, bool KSB, int EPI>
__global__ __launch_bounds__(256) void tgemm(
    const float* __restrict__ Af, const __nv_bfloat16* __restrict__ Ahi,
    const __nv_bfloat16* __restrict__ Alo, int lda, long batA,
    const float* __restrict__ Bf, const __nv_bfloat16* __restrict__ Bhi,
    const __nv_bfloat16* __restrict__ Blo, int ldb, long batB,
    float* __restrict__ Cf, __nv_bfloat16* __restrict__ Chi,
    __nv_bfloat16* __restrict__ Clo, int ldc, long batC,
    int Kloc,
    const float* __restrict__ ksA, int ksAstr,
    const float* __restrict__ ksB, int ksBstr,
    const float* __restrict__ biasR, const float* __restrict__ biasC,
    const float* __restrict__ scale, int scaleStr,
    const float* __restrict__ Xmat, const float* __restrict__ Ymat,
    float* __restrict__ outg)
{
    __shared__ __align__(16) __nv_bfloat16 sAh[128*LDS_], sAl[128*LDS_];
    __shared__ __align__(16) __nv_bfloat16 sBh[128*LDS_], sBl[128*LDS_];

    const int zb = blockIdx.z;
    const int m0 = blockIdx.y << 7;
    const int n0 = blockIdx.x << 7;
    const float* Afb = Af ? Af + (size_t)zb * batA : nullptr;
    const __nv_bfloat16* Ahb = Ahi ? Ahi + (size_t)zb * batA : nullptr;
    const __nv_bfloat16* Alb = Alo ? Alo + (size_t)zb * batA : nullptr;
    const float* Bfb = Bf ? Bf + (size_t)zb * batB : nullptr;
    const __nv_bfloat16* Bhb = Bhi ? Bhi + (size_t)zb * batB : nullptr;
    const __nv_bfloat16* Blb = Blo ? Blo + (size_t)zb * batB : nullptr;
    const float* kA = KSA ? (ksA + (size_t)zb * ksAstr) : nullptr;
    const float* kB = KSB ? (ksB + (size_t)zb * ksBstr) : nullptr;

    const int tid = threadIdx.x, wid = tid >> 5, lane = tid & 31;
    const int wm = (wid >> 2) * 64, wn = (wid & 3) * 32;

    float acc[4][4][4];
#pragma unroll
    for (int i = 0; i < 4; i++)
#pragma unroll
        for (int j = 0; j < 4; j++)
#pragma unroll
            for (int e = 0; e < 4; e++) acc[i][j][e] = 0.f;

    uint2 rah[4], ral[4], rbh[4], rbl[4];
    const uint32_t bAh = smem_u32(sAh), bAl = smem_u32(sAl);
    const uint32_t bBh = smem_u32(sBh), bBl = smem_u32(sBl);

    const int nch = Kloc >> 5;
    ldg_op<AF, KSA>(Afb, Ahb, Alb, lda, m0, 0, kA, tid, rah, ral);
    ldg_op<BF, KSB>(Bfb, Bhb, Blb, ldb, n0, 0, kB, tid, rbh, rbl);

    for (int ch = 0; ch < nch; ch++) {
        sts_op<AF>(rah, ral, sAh, sAl, tid);
        sts_op<BF>(rbh, rbl, sBh, sBl, tid);
        __syncthreads();
        if (ch + 1 < nch) {
            int kk = (ch + 1) << 5;
            ldg_op<AF, KSA>(Afb, Ahb, Alb, lda, m0, kk, kA, tid, rah, ral);
            ldg_op<BF, KSB>(Bfb, Bhb, Blb, ldb, n0, kk, kB, tid, rbh, rbl);
        }
#pragma unroll
        for (int ks = 0; ks < 2; ks++) {
            uint32_t afh[4][4], afl[4][4];
#pragma unroll
            for (int mt = 0; mt < 4; mt++) {
                uint32_t aoff = (uint32_t)((wm + mt * 16 + (lane & 15)) * LDS_
                                           + ks * 16 + ((lane >> 4) << 3)) * 2u;
                LDSM_X4(afh[mt], bAh + aoff);
                LDSM_X4(afl[mt], bAl + aoff);
            }
            uint32_t bfh[2][4], bfl[2][4];
#pragma unroll
            for (int nt = 0; nt < 2; nt++) {
                uint32_t boff = (uint32_t)((wn + nt * 16 + ((lane >> 4) << 3) + (lane & 7)) * LDS_
                                           + ks * 16 + (((lane >> 3) & 1) << 3)) * 2u;
                LDSM_X4(bfh[nt], bBh + boff);
                LDSM_X4(bfl[nt], bBl + boff);
            }
#pragma unroll
            for (int mt = 0; mt < 4; mt++)
#pragma unroll
                for (int nt = 0; nt < 2; nt++)
#pragma unroll
                    for (int h = 0; h < 2; h++) {
                        float* c = acc[mt][nt * 2 + h];
                        MMA_BF16(c, afh[mt], bfh[nt][2 * h], bfh[nt][2 * h + 1]);
                        MMA_BF16(c, afh[mt], bfl[nt][2 * h], bfl[nt][2 * h + 1]);
                        MMA_BF16(c, afl[mt], bfh[nt][2 * h], bfh[nt][2 * h + 1]);
                    }
        }
        __syncthreads();
    }

    // epilogue
#pragma unroll
    for (int mt = 0; mt < 4; mt++) {
        int r0 = m0 + wm + mt * 16 + (lane >> 2);
        int r1 = r0 + 8;
        float s0 = 1.f, s1 = 1.f, br0 = 0.f, br1 = 0.f;
        if constexpr (EPI == 2) { s0 = scale[zb * scaleStr + r0]; s1 = scale[zb * scaleStr + r1]; }
        if constexpr (EPI == 1) { br0 = biasR[zb * LC + r0]; br1 = biasR[zb * LC + r1]; }
#pragma unroll
        for (int nt = 0; nt < 4; nt++) {
            int col = n0 + wn + nt * 8 + (lane & 3) * 2;
            float2 v0, v1;
            v0.x = acc[mt][nt][0]; v0.y = acc[mt][nt][1];
            v1.x = acc[mt][nt][2]; v1.y = acc[mt][nt][3];
            if constexpr (EPI == 1) {
                float bc0 = biasC[zb * LQ + col], bc1 = biasC[zb * LQ + col + 1];
                v0.x = __expf(v0.x + br0 + bc0); v0.y = __expf(v0.y + br0 + bc1);
                v1.x = __expf(v1.x + br1 + bc0); v1.y = __expf(v1.y + br1 + bc1);
                size_t b0 = (size_t)zb * batC + (size_t)r0 * ldc + col;
                size_t b1 = (size_t)zb * batC + (size_t)r1 * ldc + col;
                uint32_t h0 = pack_bf2(v0.x, v0.y);
                uint32_t h1 = pack_bf2(v1.x, v1.y);
                float h0x = __bfloat162float(__float2bfloat16(v0.x));
                float h0y = __bfloat162float(__float2bfloat16(v0.y));
                float h1x = __bfloat162float(__float2bfloat16(v1.x));
                float h1y = __bfloat162float(__float2bfloat16(v1.y));
                uint32_t l0 = pack_bf2(v0.x - h0x, v0.y - h0y);
                uint32_t l1 = pack_bf2(v1.x - h1x, v1.y - h1y);
                *reinterpret_cast<uint32_t*>(Chi + b0) = h0;
                *reinterpret_cast<uint32_t*>(Chi + b1) = h1;
                *reinterpret_cast<uint32_t*>(Clo + b0) = l0;
                *reinterpret_cast<uint32_t*>(Clo + b1) = l1;
            }
            if constexpr (EPI == 2) {
                v0.x *= s0; v0.y *= s0; v1.x *= s1; v1.y *= s1;
                float* Cb = Cf + (size_t)zb * batC;
                *reinterpret_cast<float2*>(Cb + (size_t)r0 * ldc + col) = v0;
                *reinterpret_cast<float2*>(Cb + (size_t)r1 * ldc + col) = v1;
            }
            if constexpr (EPI == 3) {
                float c0 = scale[zb * scaleStr + col], c1v = scale[zb * scaleStr + col + 1];
                v0.x *= c0; v0.y *= c1v; v1.x *= c0; v1.y *= c1v;
                float* Cb = Cf + (size_t)zb * batC;
                *reinterpret_cast<float2*>(Cb + (size_t)r0 * ldc + col) = v0;
                *reinterpret_cast<float2*>(Cb + (size_t)r1 * ldc + col) = v1;
            }
            if constexpr (EPI == 4) {
                float c0 = scale[zb * scaleStr + col], c1v = scale[zb * scaleStr + col + 1];
                v0.x *= c0; v0.y *= c1v; v1.x *= c0; v1.y *= c1v;
                size_t zo = (size_t)zb * D_ * LC;
                float2 cc0 = *reinterpret_cast<const float2*>(Xmat + zo + (size_t)r0 * LC + col);
                float2 cc1 = *reinterpret_cast<const float2*>(Xmat + zo + (size_t)r1 * LC + col);
                float2 aa0 = *reinterpret_cast<const float2*>(Ymat + zo + (size_t)r0 * LC + col);
                float2 aa1 = *reinterpret_cast<const float2*>(Ymat + zo + (size_t)r1 * LC + col);
                float* O = outg + (size_t)zb * 4 * D_ * LC;
                *reinterpret_cast<float2*>(O + (size_t)r0 * LC + col) = cc0;
                *reinterpret_cast<float2*>(O + (size_t)r1 * LC + col) = cc1;
                *reinterpret_cast<float2*>(O + (size_t)(D_ + r0) * LC + col) = aa0;
                *reinterpret_cast<float2*>(O + (size_t)(D_ + r1) * LC + col) = aa1;
                float2 m0v, m1v;
                m0v.x = cc0.x * aa0.x; m0v.y = cc0.y * aa0.y;
                m1v.x = cc1.x * aa1.x; m1v.y = cc1.y * aa1.y;
                *reinterpret_cast<float2*>(O + (size_t)(2 * D_ + r0) * LC + col) = m0v;
                *reinterpret_cast<float2*>(O + (size_t)(2 * D_ + r1) * LC + col) = m1v;
                float2 b0v, b1v;
                b0v.x = cc0.x * v0.x; b0v.y = cc0.y * v0.y;
                b1v.x = cc1.x * v1.x; b1v.y = cc1.y * v1.y;
                *reinterpret_cast<float2*>(O + (size_t)(3 * D_ + r0) * LC + col) = b0v;
                *reinterpret_cast<float2*>(O + (size_t)(3 * D_ + r1) * LC + col) = b1v;
            }
        }
    }
}

// ---------------- K1: bias vectors c1[l] = Ct.w1, q2[m] = Qt.w2 ----------------
__global__ void k_bias(const float* __restrict__ C, const float* __restrict__ Q,
                       const float* __restrict__ w) {
    int b = blockIdx.y, seg = blockIdx.x, t = threadIdx.x;
    if (seg < 4) {
        int l = seg * 256 + t;
        const float* Cb = C + (size_t)b * D_ * LC;
        float acc = 0.f;
#pragma unroll 8
        for (int d = 0; d < D_; d++) acc += Cb[(size_t)d * LC + l] * __ldg(w + d);
        g_c1[b * LC + l] = acc;
    } else {
        int m = t;
        const float* Qb = Q + (size_t)b * D_ * LQ;
        float acc = 0.f;
#pragma unroll 8
        for (int d = 0; d < D_; d++) acc += Qb[(size_t)d * LQ + m] * __ldg(w + D_ + d);
        g_q2[b * LQ + m] = acc;
    }
}

// ---------------- sums over bf16-pair E ----------------
__device__ __forceinline__ void unp8(uint4 H, uint4 L, float* e) {
    auto f2 = [](uint32_t u) {
        __nv_bfloat162 t = *reinterpret_cast<__nv_bfloat162*>(&u);
        return make_float2(__bfloat162float(t.x), __bfloat162float(t.y));
    };
    float2 a = f2(H.x), b = f2(H.y), c = f2(H.z), d = f2(H.w);
    float2 la = f2(L.x), lb = f2(L.y), lc = f2(L.z), ld = f2(L.w);
    e[0] = a.x + la.x; e[1] = a.y + la.y; e[2] = b.x + lb.x; e[3] = b.y + lb.y;
    e[4] = c.x + lc.x; e[5] = c.y + lc.y; e[6] = d.x + ld.x; e[7] = d.y + ld.y;
}

__global__ __launch_bounds__(256) void k_sums(const float* __restrict__ qmask,
                                              const float* __restrict__ cmask) {
    int b = blockIdx.y, rc = blockIdx.x;
    int w = threadIdx.x >> 5, lane = threadIdx.x & 31;
    __shared__ float cp[8][256];
    float q[8];
    float4 q0 = *reinterpret_cast<const float4*>(qmask + b * LQ + lane * 8);
    float4 q1 = *reinterpret_cast<const float4*>(qmask + b * LQ + lane * 8 + 4);
    q[0] = q0.x; q[1] = q0.y; q[2] = q0.z; q[3] = q0.w;
    q[4] = q1.x; q[5] = q1.y; q[6] = q1.z; q[7] = q1.w;
    float col[8] = {0.f, 0.f, 0.f, 0.f, 0.f, 0.f, 0.f, 0.f};
#pragma unroll 4
    for (int rr = 0; rr < 16; rr++) {
        int l = rc * 128 + w * 16 + rr;
        size_t rowoff = ((size_t)b * LC + l) * LQ;
        uint4 H = reinterpret_cast<const uint4*>(g_Ehi + rowoff)[lane];
        uint4 L = reinterpret_cast<const uint4*>(g_Elo + rowoff)[lane];
        float e[8]; unp8(H, L, e);
        float cm = cmask[b * LC + l];
        float s = 0.f;
#pragma unroll
        for (int j = 0; j < 8; j++) { col[j] += e[j] * cm; s += e[j] * q[j]; }
#pragma unroll
        for (int o = 16; o; o >>= 1) s += __shfl_xor_sync(0xffffffffu, s, o);
        if (lane == 0) g_rinv[b * LC + l] = 1.f / s;
    }
#pragma unroll
    for (int j = 0; j < 8; j++) cp[w][lane * 8 + j] = col[j];
    __syncthreads();
    int m = threadIdx.x;
    float c = cp[0][m] + cp[1][m] + cp[2][m] + cp[3][m]
            + cp[4][m] + cp[5][m] + cp[6][m] + cp[7][m];
    g_cpart[(b * 8 + rc) * 256 + m] = c;
}

__global__ void k_colfin(const float* __restrict__ qmask) {
    int b = blockIdx.x, m = threadIdx.x;
    const float* p = g_cpart + b * 8 * 256 + m;
    float c = p[0] + p[256] + p[512] + p[768] + p[1024] + p[1280] + p[1536] + p[1792];
    g_qcinv[b * LQ + m] = qmask[b * LQ + m] / c;
}

// ---------------- launch ----------------
extern "C" void kernel_launch(void* const* d_in, const int* in_sizes, int n_in,
                              void* d_out, int out_size) {
    const float* C     = (const float*)d_in[0];
    const float* Q     = (const float*)d_in[1];
    const float* cmask = (const float*)d_in[2];
    const float* qmask = (const float*)d_in[3];
    const float* w     = (const float*)d_in[4];
    float* out = (float*)d_out;

    __nv_bfloat16 *pEhi, *pElo;
    float *pAt, *pT, *pc1, *pq2, *prv, *pqc;
    cudaGetSymbolAddress((void**)&pEhi, g_Ehi);
    cudaGetSymbolAddress((void**)&pElo, g_Elo);
    cudaGetSymbolAddress((void**)&pAt,  g_At);
    cudaGetSymbolAddress((void**)&pT,   g_T);
    cudaGetSymbolAddress((void**)&pc1,  g_c1);
    cudaGetSymbolAddress((void**)&pq2,  g_q2);
    cudaGetSymbolAddress((void**)&prv,  g_rinv);
    cudaGetSymbolAddress((void**)&pqc,  g_qcinv);

    // K1: bias vectors
    k_bias<<<dim3(5, B_), 256>>>(C, Q, w);

    // G1: E = exp((C*w3)^T Q + c1 + q2) -> bf16 hi/lo   [m=l (8 tiles), n=m' (2), K=D]
    tgemm<1, 1, true, false, 1><<<dim3(2, 8, B_), 256>>>(
        C, nullptr, nullptr, LC, (long)D_ * LC,
        Q, nullptr, nullptr, LQ, (long)D_ * LQ,
        nullptr, pEhi, pElo, LQ, (long)LC * LQ,
        D_,
        w + 2 * D_, 0,  nullptr, 0,
        pc1, pq2,  nullptr, 0,  nullptr, nullptr, nullptr);

    // sums -> rinv, col partials -> qcinv
    k_sums<<<dim3(8, B_), 256>>>(qmask, cmask);
    k_colfin<<<B_, 256>>>(qmask);

    // G3: T[m'][d] = (sum_l E(l,m')*cm(l)*C(d,l)) * qcinv(m')   [m=m' (2), n=d (1), K=Lc]
    // A = E^T bf16-pair TRANS; B = C fp32 K-fast with kscale cmask; EPI=2 scale rows
    tgemm<3, 0, false, true, 2><<<dim3(1, 2, B_), 256>>>(
        nullptr, pEhi, pElo, LQ, (long)LC * LQ,
        C, nullptr, nullptr, LC, (long)D_ * LC,
        pT, nullptr, nullptr, D_, (long)LQ * D_,
        LC,
        nullptr, 0,  cmask, LC,
        nullptr, nullptr,  pqc, LQ,  nullptr, nullptr, nullptr);

    // G2: At[d][l] = (sum_m' Q(d,m')*qm(m')*E(l,m')) * rinv(l)   [m=d (1), n=l (8), K=Lq]
    tgemm<0, 2, true, false, 3><<<dim3(8, 1, B_), 256>>>(
        Q, nullptr, nullptr, LQ, (long)D_ * LQ,
        nullptr, pEhi, pElo, LQ, (long)LC * LQ,
        pAt, nullptr, nullptr, LC, (long)D_ * LC,
        LQ,
        qmask, LQ,  nullptr, 0,
        nullptr, nullptr,  prv, LC,  nullptr, nullptr, nullptr);

    // G4: Bv^T[d][l] = (sum_m' T(m',d)*E(l,m')) * rinv(l); fused final output
    tgemm<1, 2, false, false, 4><<<dim3(8, 1, B_), 256>>>(
        pT, nullptr, nullptr, D_, (long)LQ * D_,
        nullptr, pEhi, pElo, LQ, (long)LC * LQ,
        nullptr, nullptr, nullptr, LC, (long)D_ * LC,
        LQ,
        nullptr, 0,  nullptr, 0,
        nullptr, nullptr,  prv, LC,  C, pAt, out);
}

// round 8
// speedup vs baseline: 1.0678x; 1.0678x over previous
#include <cuda_runtime.h>
#include <cuda_bf16.h>
#include <cstdint>

#define B_  64
#define D_  128
#define LC  1024
#define LQ  256
#define LDS_ 40      // smem row stride in bf16 elements (conflict-free for ldmatrix)

// ---------------- scratch (static device arrays) ----------------
static __device__ float g_E   [(size_t)B_*LC*LQ];    // exp(S + biases), unnormalized
static __device__ float g_At  [(size_t)B_*D_*LC];    // A^T  [d][l]
static __device__ float g_Tp  [(size_t)B_*2*LQ*D_];  // split-K partials for T
static __device__ float g_T   [(size_t)B_*LQ*D_];    // T-hat [m][d] (qm*cinv folded)
static __device__ float g_rinv[B_*LC];
static __device__ float g_qcinv[B_*LQ];
static __device__ float g_cpart[B_*8*LQ];
static __device__ float g_c1[B_*LC];
static __device__ float g_q2[B_*LQ];

// ---------------- helpers ----------------
__device__ __forceinline__ uint32_t smem_u32(const void* p) {
    uint32_t a;
    asm("{ .reg .u64 t; cvta.to.shared.u64 t, %1; cvt.u32.u64 %0, t; }" : "=r"(a) : "l"(p));
    return a;
}

#define LDSM_X4(r, a) \
    asm volatile("ldmatrix.sync.aligned.m8n8.x4.shared.b16 {%0,%1,%2,%3}, [%4];" \
        : "=r"((r)[0]), "=r"((r)[1]), "=r"((r)[2]), "=r"((r)[3]) : "r"(a))

#define MMA_BF16(c, a, b0, b1) \
    asm volatile("mma.sync.aligned.m16n8k16.row.col.f32.bf16.bf16.f32 " \
        "{%0,%1,%2,%3}, {%4,%5,%6,%7}, {%8,%9}, {%0,%1,%2,%3};" \
        : "+f"((c)[0]), "+f"((c)[1]), "+f"((c)[2]), "+f"((c)[3]) \
        : "r"((a)[0]), "r"((a)[1]), "r"((a)[2]), "r"((a)[3]), "r"(b0), "r"(b1))

// ---------------- operand loaders ----------------
// logical: element (mn, klocal) -> smem[mn*LDS_ + klocal]
// TRANS=false: src element (mn, k) at src[mn*ld + k]  (K contiguous)
// TRANS=true : src element (mn, k) at src[k*ld + mn]  (MN contiguous) -> load along K
template<bool TRANS, bool KS>
__device__ __forceinline__ void ldg_op(const float* __restrict__ src, int ld, int mn0,
                                       int kk, const float* __restrict__ ks,
                                       int tid, float4 (&r)[4]) {
#pragma unroll
    for (int i = 0; i < 4; i++) {
        int v = i * 256 + tid;
        if constexpr (!TRANS) {
            int row = v >> 3, c4 = v & 7;
            float4 x = *reinterpret_cast<const float4*>(src + (size_t)(mn0 + row) * ld + kk + c4 * 4);
            if constexpr (KS) {
                float4 s = *reinterpret_cast<const float4*>(ks + kk + c4 * 4);
                x.x *= s.x; x.y *= s.y; x.z *= s.z; x.w *= s.w;
            }
            r[i] = x;
        } else {
            int mn = v & 127, krb = v >> 7;          // krb in [0,8): k = krb*4..+3
            const float* p = src + (size_t)(kk + krb * 4) * ld + mn0 + mn;
            float4 x;
            x.x = p[0]; x.y = p[ld]; x.z = p[2 * (size_t)ld]; x.w = p[3 * (size_t)ld];
            if constexpr (KS) {
                const float* s = ks + kk + krb * 4;
                x.x *= s[0]; x.y *= s[1]; x.z *= s[2]; x.w *= s[3];
            }
            r[i] = x;
        }
    }
}

template<bool TRANS>
__device__ __forceinline__ void sts_op(float4 (&r)[4], __nv_bfloat16* smh, __nv_bfloat16* sml, int tid) {
#pragma unroll
    for (int i = 0; i < 4; i++) {
        float vv[4] = {r[i].x, r[i].y, r[i].z, r[i].w};
        __nv_bfloat16 hv[4], lv[4];
#pragma unroll
        for (int e = 0; e < 4; e++) {
            hv[e] = __float2bfloat16(vv[e]);
            lv[e] = __float2bfloat16(vv[e] - __bfloat162float(hv[e]));
        }
        int v = i * 256 + tid;
        int off;
        if constexpr (!TRANS) { int row = v >> 3, c4 = v & 7; off = row * LDS_ + c4 * 4; }
        else                  { int mn = v & 127, krb = v >> 7; off = mn * LDS_ + krb * 4; }
        __nv_bfloat162 h01(hv[0], hv[1]), h23(hv[2], hv[3]);
        __nv_bfloat162 l01(lv[0], lv[1]), l23(lv[2], lv[3]);
        uint2 uh, ul;
        uh.x = *reinterpret_cast<uint32_t*>(&h01); uh.y = *reinterpret_cast<uint32_t*>(&h23);
        ul.x = *reinterpret_cast<uint32_t*>(&l01); ul.y = *reinterpret_cast<uint32_t*>(&l23);
        *reinterpret_cast<uint2*>(smh + off) = uh;
        *reinterpret_cast<uint2*>(sml + off) = ul;
    }
}

// ---------------- bf16 3-pass tensor GEMM: Out(m,n) = sum_k A(m,k)*B(n,k) ----------------
// EPI 0: plain fp32 store (split-K partial)
// EPI 1: exp(acc + biasR[row] + biasC[col]) -> fp32
// EPI 2: acc * scale[row] -> fp32
// EPI 3: acc * scale[col] -> fp32
// EPI 4: bv = acc * scale[col]; load Xmat(row,col)=C, Ymat(row,col)=At; write 4 output channels
template<bool AT, bool BT, bool KSA, bool KSB, int EPI>
__global__ __launch_bounds__(256) void tgemm(
    const float* __restrict__ Ag, int lda, long batA,
    const float* __restrict__ Bg, int ldb, long batB,
    float* __restrict__ Cg, int ldc, long batC,
    int Kloc, int nsplit,
    const float* __restrict__ ksA, int ksAstr,
    const float* __restrict__ ksB, int ksBstr,
    const float* __restrict__ biasR, const float* __restrict__ biasC,
    const float* __restrict__ scale, int scaleStr,
    const float* __restrict__ Xmat, const float* __restrict__ Ymat,
    float* __restrict__ outg)
{
    __shared__ __align__(16) __nv_bfloat16 sAh[128*LDS_], sAl[128*LDS_];
    __shared__ __align__(16) __nv_bfloat16 sBh[128*LDS_], sBl[128*LDS_];

    const int zb = blockIdx.z / nsplit;
    const int sp = blockIdx.z - zb * nsplit;
    const int k0 = sp * Kloc;
    const int m0 = blockIdx.y << 7;
    const int n0 = blockIdx.x << 7;
    const float* Ab = Ag + (size_t)zb * batA;
    const float* Bb = Bg + (size_t)zb * batB;
    const float* kA = KSA ? (ksA + (size_t)zb * ksAstr) : nullptr;
    const float* kB = KSB ? (ksB + (size_t)zb * ksBstr) : nullptr;

    const int tid = threadIdx.x, wid = tid >> 5, lane = tid & 31;
    const int wm = (wid >> 2) * 64, wn = (wid & 3) * 32;

    float acc[4][4][4];
#pragma unroll
    for (int i = 0; i < 4; i++)
#pragma unroll
        for (int j = 0; j < 4; j++)
#pragma unroll
            for (int e = 0; e < 4; e++) acc[i][j][e] = 0.f;

    float4 ra[4], rb[4];
    const uint32_t bAh = smem_u32(sAh), bAl = smem_u32(sAl);
    const uint32_t bBh = smem_u32(sBh), bBl = smem_u32(sBl);

    const int nch = Kloc >> 5;
    ldg_op<AT, KSA>(Ab, lda, m0, k0, kA, tid, ra);
    ldg_op<BT, KSB>(Bb, ldb, n0, k0, kB, tid, rb);

    for (int ch = 0; ch < nch; ch++) {
        sts_op<AT>(ra, sAh, sAl, tid);
        sts_op<BT>(rb, sBh, sBl, tid);
        __syncthreads();
        if (ch + 1 < nch) {
            int kk = k0 + ((ch + 1) << 5);
            ldg_op<AT, KSA>(Ab, lda, m0, kk, kA, tid, ra);
            ldg_op<BT, KSB>(Bb, ldb, n0, kk, kB, tid, rb);
        }
#pragma unroll
        for (int ks = 0; ks < 2; ks++) {
            uint32_t afh[4][4], afl[4][4];
#pragma unroll
            for (int mt = 0; mt < 4; mt++) {
                uint32_t aoff = (uint32_t)((wm + mt * 16 + (lane & 15)) * LDS_
                                           + ks * 16 + ((lane >> 4) << 3)) * 2u;
                LDSM_X4(afh[mt], bAh + aoff);
                LDSM_X4(afl[mt], bAl + aoff);
            }
            uint32_t bfh[2][4], bfl[2][4];
#pragma unroll
            for (int nt = 0; nt < 2; nt++) {
                uint32_t boff = (uint32_t)((wn + nt * 16 + ((lane >> 4) << 3) + (lane & 7)) * LDS_
                                           + ks * 16 + (((lane >> 3) & 1) << 3)) * 2u;
                LDSM_X4(bfh[nt], bBh + boff);
                LDSM_X4(bfl[nt], bBl + boff);
            }
#pragma unroll
            for (int mt = 0; mt < 4; mt++)
#pragma unroll
                for (int nt = 0; nt < 2; nt++)
#pragma unroll
                    for (int h = 0; h < 2; h++) {
                        float* c = acc[mt][nt * 2 + h];
                        MMA_BF16(c, afh[mt], bfh[nt][2 * h], bfh[nt][2 * h + 1]);
                        MMA_BF16(c, afh[mt], bfl[nt][2 * h], bfl[nt][2 * h + 1]);
                        MMA_BF16(c, afl[mt], bfh[nt][2 * h], bfh[nt][2 * h + 1]);
                    }
        }
        __syncthreads();
    }

    // epilogue
#pragma unroll
    for (int mt = 0; mt < 4; mt++) {
        int r0 = m0 + wm + mt * 16 + (lane >> 2);
        int r1 = r0 + 8;
        float s0 = 1.f, s1 = 1.f, br0 = 0.f, br1 = 0.f;
        if constexpr (EPI == 2) { s0 = scale[zb * scaleStr + r0]; s1 = scale[zb * scaleStr + r1]; }
        if constexpr (EPI == 1) { br0 = biasR[zb * LC + r0]; br1 = biasR[zb * LC + r1]; }
#pragma unroll
        for (int nt = 0; nt < 4; nt++) {
            int col = n0 + wn + nt * 8 + (lane & 3) * 2;
            float2 v0, v1;
            v0.x = acc[mt][nt][0]; v0.y = acc[mt][nt][1];
            v1.x = acc[mt][nt][2]; v1.y = acc[mt][nt][3];
            if constexpr (EPI == 0) {
                float* Cb = Cg + (size_t)blockIdx.z * batC;
                *reinterpret_cast<float2*>(Cb + (size_t)r0 * ldc + col) = v0;
                *reinterpret_cast<float2*>(Cb + (size_t)r1 * ldc + col) = v1;
            }
            if constexpr (EPI == 1) {
                float bc0 = biasC[zb * LQ + col], bc1 = biasC[zb * LQ + col + 1];
                v0.x = __expf(v0.x + br0 + bc0); v0.y = __expf(v0.y + br0 + bc1);
                v1.x = __expf(v1.x + br1 + bc0); v1.y = __expf(v1.y + br1 + bc1);
                float* Cb = Cg + (size_t)blockIdx.z * batC;
                *reinterpret_cast<float2*>(Cb + (size_t)r0 * ldc + col) = v0;
                *reinterpret_cast<float2*>(Cb + (size_t)r1 * ldc + col) = v1;
            }
            if constexpr (EPI == 2) {
                v0.x *= s0; v0.y *= s0; v1.x *= s1; v1.y *= s1;
                float* Cb = Cg + (size_t)blockIdx.z * batC;
                *reinterpret_cast<float2*>(Cb + (size_t)r0 * ldc + col) = v0;
                *reinterpret_cast<float2*>(Cb + (size_t)r1 * ldc + col) = v1;
            }
            if constexpr (EPI == 3) {
                float c0 = scale[zb * scaleStr + col], c1v = scale[zb * scaleStr + col + 1];
                v0.x *= c0; v0.y *= c1v; v1.x *= c0; v1.y *= c1v;
                float* Cb = Cg + (size_t)blockIdx.z * batC;
                *reinterpret_cast<float2*>(Cb + (size_t)r0 * ldc + col) = v0;
                *reinterpret_cast<float2*>(Cb + (size_t)r1 * ldc + col) = v1;
            }
            if constexpr (EPI == 4) {
                float c0 = scale[zb * scaleStr + col], c1v = scale[zb * scaleStr + col + 1];
                v0.x *= c0; v0.y *= c1v; v1.x *= c0; v1.y *= c1v;
                size_t zo = (size_t)zb * D_ * LC;
                float2 cc0 = *reinterpret_cast<const float2*>(Xmat + zo + (size_t)r0 * LC + col);
                float2 cc1 = *reinterpret_cast<const float2*>(Xmat + zo + (size_t)r1 * LC + col);
                float2 aa0 = *reinterpret_cast<const float2*>(Ymat + zo + (size_t)r0 * LC + col);
                float2 aa1 = *reinterpret_cast<const float2*>(Ymat + zo + (size_t)r1 * LC + col);
                float* O = outg + (size_t)zb * 4 * D_ * LC;
                *reinterpret_cast<float2*>(O + (size_t)r0 * LC + col) = cc0;
                *reinterpret_cast<float2*>(O + (size_t)r1 * LC + col) = cc1;
                *reinterpret_cast<float2*>(O + (size_t)(D_ + r0) * LC + col) = aa0;
                *reinterpret_cast<float2*>(O + (size_t)(D_ + r1) * LC + col) = aa1;
                float2 m0v, m1v;
                m0v.x = cc0.x * aa0.x; m0v.y = cc0.y * aa0.y;
                m1v.x = cc1.x * aa1.x; m1v.y = cc1.y * aa1.y;
                *reinterpret_cast<float2*>(O + (size_t)(2 * D_ + r0) * LC + col) = m0v;
                *reinterpret_cast<float2*>(O + (size_t)(2 * D_ + r1) * LC + col) = m1v;
                float2 b0v, b1v;
                b0v.x = cc0.x * v0.x; b0v.y = cc0.y * v0.y;
                b1v.x = cc1.x * v1.x; b1v.y = cc1.y * v1.y;
                *reinterpret_cast<float2*>(O + (size_t)(3 * D_ + r0) * LC + col) = b0v;
                *reinterpret_cast<float2*>(O + (size_t)(3 * D_ + r1) * LC + col) = b1v;
            }
        }
    }
}

// ---------------- K1: bias vectors c1[l] = Ct.w1, q2[m] = Qt.w2 ----------------
__global__ void k_bias(const float* __restrict__ C, const float* __restrict__ Q,
                       const float* __restrict__ w) {
    int b = blockIdx.y, seg = blockIdx.x, t = threadIdx.x;
    if (seg < 4) {
        int l = seg * 256 + t;
        const float* Cb = C + (size_t)b * D_ * LC;
        float acc = 0.f;
#pragma unroll 8
        for (int d = 0; d < D_; d++) acc += Cb[(size_t)d * LC + l] * __ldg(w + d);
        g_c1[b * LC + l] = acc;
    } else {
        int m = t;
        const float* Qb = Q + (size_t)b * D_ * LQ;
        float acc = 0.f;
#pragma unroll 8
        for (int d = 0; d < D_; d++) acc += Qb[(size_t)d * LQ + m] * __ldg(w + D_ + d);
        g_q2[b * LQ + m] = acc;
    }
}

// ---------------- sums: rinv[l] = 1/sum_m E*qm, col partials for cinv ----------------
__global__ __launch_bounds__(256) void k_sums(const float* __restrict__ qmask,
                                              const float* __restrict__ cmask) {
    int b = blockIdx.y, rc = blockIdx.x;
    int w = threadIdx.x >> 5, lane = threadIdx.x & 31;
    __shared__ float cp[8][256];
    float4 q0 = *reinterpret_cast<const float4*>(qmask + b * LQ + lane * 4);
    float4 q1 = *reinterpret_cast<const float4*>(qmask + b * LQ + 128 + lane * 4);
    float col[8] = {0.f, 0.f, 0.f, 0.f, 0.f, 0.f, 0.f, 0.f};
#pragma unroll 4
    for (int rr = 0; rr < 16; rr++) {
        int l = rc * 128 + w * 16 + rr;
        const float* Er = g_E + ((size_t)b * LC + l) * LQ;
        float4 e0 = *reinterpret_cast<const float4*>(Er + lane * 4);
        float4 e1 = *reinterpret_cast<const float4*>(Er + 128 + lane * 4);
        float cm = cmask[b * LC + l];
        col[0] += e0.x * cm; col[1] += e0.y * cm; col[2] += e0.z * cm; col[3] += e0.w * cm;
        col[4] += e1.x * cm; col[5] += e1.y * cm; col[6] += e1.z * cm; col[7] += e1.w * cm;
        float s = e0.x * q0.x + e0.y * q0.y + e0.z * q0.z + e0.w * q0.w
                + e1.x * q1.x + e1.y * q1.y + e1.z * q1.z + e1.w * q1.w;
#pragma unroll
        for (int o = 16; o; o >>= 1) s += __shfl_xor_sync(0xffffffffu, s, o);
        if (lane == 0) g_rinv[b * LC + l] = 1.f / s;
    }
#pragma unroll
    for (int j = 0; j < 4; j++) {
        cp[w][lane * 4 + j] = col[j];
        cp[w][128 + lane * 4 + j] = col[4 + j];
    }
    __syncthreads();
    int m = threadIdx.x;
    float c = cp[0][m] + cp[1][m] + cp[2][m] + cp[3][m]
            + cp[4][m] + cp[5][m] + cp[6][m] + cp[7][m];
    g_cpart[(b * 8 + rc) * 256 + m] = c;
}

__global__ void k_colfin(const float* __restrict__ qmask) {
    int b = blockIdx.x, m = threadIdx.x;
    const float* p = g_cpart + b * 8 * 256 + m;
    float c = p[0] + p[256] + p[512] + p[768] + p[1024] + p[1280] + p[1536] + p[1792];
    g_qcinv[b * LQ + m] = qmask[b * LQ + m] / c;
}

// ---------------- reduce split-K partials of T, apply qm*cinv ----------------
__global__ void k_redT() {
    int idx = blockIdx.x * 256 + threadIdx.x;      // < B*LQ*D = 2097152
    int b = idx >> 15;                             // LQ*D = 32768
    int off = idx & 32767;
    int m = off >> 7;                              // D_ = 128
    size_t base = ((size_t)b * 2) * 32768 + off;
    g_T[idx] = (g_Tp[base] + g_Tp[base + 32768]) * g_qcinv[b * LQ + m];
}

// ---------------- launch ----------------
extern "C" void kernel_launch(void* const* d_in, const int* in_sizes, int n_in,
                              void* d_out, int out_size) {
    const float* C     = (const float*)d_in[0];
    const float* Q     = (const float*)d_in[1];
    const float* cmask = (const float*)d_in[2];
    const float* qmask = (const float*)d_in[3];
    const float* w     = (const float*)d_in[4];
    float* out = (float*)d_out;

    float *pE, *pAt, *pTp, *pT, *pc1, *pq2, *prv;
    cudaGetSymbolAddress((void**)&pE,   g_E);
    cudaGetSymbolAddress((void**)&pAt,  g_At);
    cudaGetSymbolAddress((void**)&pTp,  g_Tp);
    cudaGetSymbolAddress((void**)&pT,   g_T);
    cudaGetSymbolAddress((void**)&pc1,  g_c1);
    cudaGetSymbolAddress((void**)&pq2,  g_q2);
    cudaGetSymbolAddress((void**)&prv,  g_rinv);

    // K1: bias vectors
    k_bias<<<dim3(5, B_), 256>>>(C, Q, w);

    // G1: E = exp((C*w3)^T Q + c1 + q2)  [m=l (8 tiles), n=m' (2), K=D]
    tgemm<true, true, true, false, 1><<<dim3(2, 8, B_), 256>>>(
        C, LC, (long)D_ * LC,  Q, LQ, (long)D_ * LQ,
        pE, LQ, (long)LC * LQ,  D_, 1,
        w + 2 * D_, 0,  nullptr, 0,
        pc1, pq2,  nullptr, 0,  nullptr, nullptr, nullptr);

    // sums -> rinv, col partials -> qcinv
    k_sums<<<dim3(8, B_), 256>>>(qmask, cmask);
    k_colfin<<<B_, 256>>>(qmask);

    // G3: Tp[b][sp][m'][d] = sum_{l in split} E(l,m')*cm(l)*C(d,l)   split-K 2
    tgemm<true, false, false, true, 0><<<dim3(1, 2, B_ * 2), 256>>>(
        pE, LQ, (long)LC * LQ,  C, LC, (long)D_ * LC,
        pTp, D_, (long)LQ * D_,  LC / 2, 2,
        nullptr, 0,  cmask, LC,
        nullptr, nullptr,  nullptr, 0,  nullptr, nullptr, nullptr);
    k_redT<<<B_ * LQ * D_ / 256, 256>>>();

    // G2: At[d][l] = (sum_m' Q(d,m')*qm(m')*E(l,m')) * rinv(l)   [m=d (1), n=l (8), K=Lq]
    tgemm<false, false, true, false, 3><<<dim3(8, 1, B_), 256>>>(
        Q, LQ, (long)D_ * LQ,  pE, LQ, (long)LC * LQ,
        pAt, LC, (long)D_ * LC,  LQ, 1,
        qmask, LQ,  nullptr, 0,
        nullptr, nullptr,  prv, LC,  nullptr, nullptr, nullptr);

    // G4: Bv^T[d][l] = (sum_m' T(m',d)*E(l,m')) * rinv(l); fused final output assembly
    tgemm<true, false, false, false, 4><<<dim3(8, 1, B_), 256>>>(
        pT, D_, (long)LQ * D_,  pE, LQ, (long)LC * LQ,
        nullptr, LC, (long)D_ * LC,  LQ, 1,
        nullptr, 0,  nullptr, 0,
        nullptr, nullptr,  prv, LC,  C, pAt, out);
}

// round 9
// speedup vs baseline: 1.1125x; 1.0419x over previous
#include <cuda_runtime.h>
#include <cuda_bf16.h>
#include <cstdint>

#define B_  64
#define D_  128
#define LC  1024
#define LQ  256
#define LDS_ 40      // smem row stride in bf16 elements (conflict-free for ldmatrix)

// ---------------- scratch (static device arrays) ----------------
static __device__ float g_E   [(size_t)B_*LC*LQ];    // exp(S + biases), unnormalized
static __device__ float g_T   [(size_t)B_*LQ*D_];    // T_raw [m'][d] (unscaled)
static __device__ float g_rinv[B_*LC];
static __device__ float g_qcinv[B_*LQ];
static __device__ float g_cpart[B_*8*LQ];
static __device__ float g_c1[B_*LC];
static __device__ float g_q2[B_*LQ];

// ---------------- helpers ----------------
__device__ __forceinline__ uint32_t smem_u32(const void* p) {
    uint32_t a;
    asm("{ .reg .u64 t; cvta.to.shared.u64 t, %1; cvt.u32.u64 %0, t; }" : "=r"(a) : "l"(p));
    return a;
}

#define LDSM_X4(r, a) \
    asm volatile("ldmatrix.sync.aligned.m8n8.x4.shared.b16 {%0,%1,%2,%3}, [%4];" \
        : "=r"((r)[0]), "=r"((r)[1]), "=r"((r)[2]), "=r"((r)[3]) : "r"(a))

#define MMA_BF16(c, a, b0, b1) \
    asm volatile("mma.sync.aligned.m16n8k16.row.col.f32.bf16.bf16.f32 " \
        "{%0,%1,%2,%3}, {%4,%5,%6,%7}, {%8,%9}, {%0,%1,%2,%3};" \
        : "+f"((c)[0]), "+f"((c)[1]), "+f"((c)[2]), "+f"((c)[3]) \
        : "r"((a)[0]), "r"((a)[1]), "r"((a)[2]), "r"((a)[3]), "r"(b0), "r"(b1))

__device__ __forceinline__ void cvt4(const float4& x, uint2& uh, uint2& ul) {
    __nv_bfloat16 hx = __float2bfloat16(x.x), hy = __float2bfloat16(x.y);
    __nv_bfloat16 hz = __float2bfloat16(x.z), hw = __float2bfloat16(x.w);
    __nv_bfloat162 h01(hx, hy), h23(hz, hw);
    __nv_bfloat162 l01(__float2bfloat16(x.x - __bfloat162float(hx)),
                       __float2bfloat16(x.y - __bfloat162float(hy)));
    __nv_bfloat162 l23(__float2bfloat16(x.z - __bfloat162float(hz)),
                       __float2bfloat16(x.w - __bfloat162float(hw)));
    uh.x = *reinterpret_cast<uint32_t*>(&h01); uh.y = *reinterpret_cast<uint32_t*>(&h23);
    ul.x = *reinterpret_cast<uint32_t*>(&l01); ul.y = *reinterpret_cast<uint32_t*>(&l23);
}

// ---------------- generic tgemm (used for G1, G3) ----------------
// logical: element (mn, klocal) -> smem[mn*LDS_ + klocal]
template<bool TRANS, bool KS>
__device__ __forceinline__ void ldg_op(const float* __restrict__ src, int ld, int mn0,
                                       int kk, const float* __restrict__ ks,
                                       int tid, float4 (&r)[4]) {
#pragma unroll
    for (int i = 0; i < 4; i++) {
        int v = i * 256 + tid;
        if constexpr (!TRANS) {
            int row = v >> 3, c4 = v & 7;
            float4 x = *reinterpret_cast<const float4*>(src + (size_t)(mn0 + row) * ld + kk + c4 * 4);
            if constexpr (KS) {
                float4 s = *reinterpret_cast<const float4*>(ks + kk + c4 * 4);
                x.x *= s.x; x.y *= s.y; x.z *= s.z; x.w *= s.w;
            }
            r[i] = x;
        } else {
            int mn = v & 127, krb = v >> 7;
            const float* p = src + (size_t)(kk + krb * 4) * ld + mn0 + mn;
            float4 x;
            x.x = p[0]; x.y = p[ld]; x.z = p[2 * (size_t)ld]; x.w = p[3 * (size_t)ld];
            if constexpr (KS) {
                const float* s = ks + kk + krb * 4;
                x.x *= s[0]; x.y *= s[1]; x.z *= s[2]; x.w *= s[3];
            }
            r[i] = x;
        }
    }
}

template<bool TRANS>
__device__ __forceinline__ void sts_op(float4 (&r)[4], __nv_bfloat16* smh, __nv_bfloat16* sml, int tid) {
#pragma unroll
    for (int i = 0; i < 4; i++) {
        int v = i * 256 + tid;
        int off;
        if constexpr (!TRANS) { int row = v >> 3, c4 = v & 7; off = row * LDS_ + c4 * 4; }
        else                  { int mn = v & 127, krb = v >> 7; off = mn * LDS_ + krb * 4; }
        uint2 uh, ul;
        cvt4(r[i], uh, ul);
        *reinterpret_cast<uint2*>(smh + off) = uh;
        *reinterpret_cast<uint2*>(sml + off) = ul;
    }
}

// EPI 0: plain fp32 ; EPI 1: exp(acc + biasR[row] + biasC[col])
template<bool AT, bool BT, bool KSA, bool KSB, int EPI>
__global__ __launch_bounds__(256) void tgemm(
    const float* __restrict__ Ag, int lda, long batA,
    const float* __restrict__ Bg, int ldb, long batB,
    float* __restrict__ Cg, int ldc, long batC,
    int Kloc,
    const float* __restrict__ ksA, int ksAstr,
    const float* __restrict__ ksB, int ksBstr,
    const float* __restrict__ biasR, const float* __restrict__ biasC)
{
    __shared__ __align__(16) __nv_bfloat16 sAh[128*LDS_], sAl[128*LDS_];
    __shared__ __align__(16) __nv_bfloat16 sBh[128*LDS_], sBl[128*LDS_];

    const int zb = blockIdx.z;
    const int m0 = blockIdx.y << 7;
    const int n0 = blockIdx.x << 7;
    const float* Ab = Ag + (size_t)zb * batA;
    const float* Bb = Bg + (size_t)zb * batB;
    const float* kA = KSA ? (ksA + (size_t)zb * ksAstr) : nullptr;
    const float* kB = KSB ? (ksB + (size_t)zb * ksBstr) : nullptr;

    const int tid = threadIdx.x, wid = tid >> 5, lane = tid & 31;
    const int wm = (wid >> 2) * 64, wn = (wid & 3) * 32;

    float acc[4][4][4];
#pragma unroll
    for (int i = 0; i < 4; i++)
#pragma unroll
        for (int j = 0; j < 4; j++)
#pragma unroll
            for (int e = 0; e < 4; e++) acc[i][j][e] = 0.f;

    float4 ra[4], rb[4];
    const uint32_t bAh = smem_u32(sAh), bAl = smem_u32(sAl);
    const uint32_t bBh = smem_u32(sBh), bBl = smem_u32(sBl);

    const int nch = Kloc >> 5;
    ldg_op<AT, KSA>(Ab, lda, m0, 0, kA, tid, ra);
    ldg_op<BT, KSB>(Bb, ldb, n0, 0, kB, tid, rb);

    for (int ch = 0; ch < nch; ch++) {
        sts_op<AT>(ra, sAh, sAl, tid);
        sts_op<BT>(rb, sBh, sBl, tid);
        __syncthreads();
        if (ch + 1 < nch) {
            int kk = (ch + 1) << 5;
            ldg_op<AT, KSA>(Ab, lda, m0, kk, kA, tid, ra);
            ldg_op<BT, KSB>(Bb, ldb, n0, kk, kB, tid, rb);
        }
#pragma unroll
        for (int ks = 0; ks < 2; ks++) {
            uint32_t afh[4][4], afl[4][4];
#pragma unroll
            for (int mt = 0; mt < 4; mt++) {
                uint32_t aoff = (uint32_t)((wm + mt * 16 + (lane & 15)) * LDS_
                                           + ks * 16 + ((lane >> 4) << 3)) * 2u;
                LDSM_X4(afh[mt], bAh + aoff);
                LDSM_X4(afl[mt], bAl + aoff);
            }
            uint32_t bfh[2][4], bfl[2][4];
#pragma unroll
            for (int nt = 0; nt < 2; nt++) {
                uint32_t boff = (uint32_t)((wn + nt * 16 + ((lane >> 4) << 3) + (lane & 7)) * LDS_
                                           + ks * 16 + (((lane >> 3) & 1) << 3)) * 2u;
                LDSM_X4(bfh[nt], bBh + boff);
                LDSM_X4(bfl[nt], bBl + boff);
            }
#pragma unroll
            for (int mt = 0; mt < 4; mt++)
#pragma unroll
                for (int nt = 0; nt < 2; nt++)
#pragma unroll
                    for (int h = 0; h < 2; h++) {
                        float* c = acc[mt][nt * 2 + h];
                        MMA_BF16(c, afh[mt], bfh[nt][2 * h], bfh[nt][2 * h + 1]);
                        MMA_BF16(c, afh[mt], bfl[nt][2 * h], bfl[nt][2 * h + 1]);
                        MMA_BF16(c, afl[mt], bfh[nt][2 * h], bfh[nt][2 * h + 1]);
                    }
        }
        __syncthreads();
    }

    float* Cb = Cg + (size_t)zb * batC;
#pragma unroll
    for (int mt = 0; mt < 4; mt++) {
        int r0 = m0 + wm + mt * 16 + (lane >> 2);
        int r1 = r0 + 8;
        float br0 = 0.f, br1 = 0.f;
        if constexpr (EPI == 1) { br0 = biasR[zb * LC + r0]; br1 = biasR[zb * LC + r1]; }
#pragma unroll
        for (int nt = 0; nt < 4; nt++) {
            int col = n0 + wn + nt * 8 + (lane & 3) * 2;
            float2 v0, v1;
            v0.x = acc[mt][nt][0]; v0.y = acc[mt][nt][1];
            v1.x = acc[mt][nt][2]; v1.y = acc[mt][nt][3];
            if constexpr (EPI == 1) {
                float bc0 = biasC[zb * LQ + col], bc1 = biasC[zb * LQ + col + 1];
                v0.x = __expf(v0.x + br0 + bc0); v0.y = __expf(v0.y + br0 + bc1);
                v1.x = __expf(v1.x + br1 + bc0); v1.y = __expf(v1.y + br1 + bc1);
            }
            *reinterpret_cast<float2*>(Cb + (size_t)r0 * ldc + col) = v0;
            *reinterpret_cast<float2*>(Cb + (size_t)r1 * ldc + col) = v1;
        }
    }
}

// ---------------- fused G2+G4: stacked A = [Q*qm ; T_raw*qcinv], B = E tile ----------------
// Out rows 0..127  : At[d][l]  (scaled by rinv[l])  -> channels 0,1,2
// Out rows 128..255: Bv[d][l]  (scaled by rinv[l])  -> channel 3
__global__ __launch_bounds__(256) void g24(
    const float* __restrict__ Q, const float* __restrict__ T,
    const float* __restrict__ E, const float* __restrict__ C,
    const float* __restrict__ qmask, const float* __restrict__ qcinv,
    const float* __restrict__ rinv, float* __restrict__ out)
{
    extern __shared__ __align__(16) char smraw[];
    __nv_bfloat16* sAh = reinterpret_cast<__nv_bfloat16*>(smraw);     // 256*LDS_
    __nv_bfloat16* sAl = sAh + 256 * LDS_;
    __nv_bfloat16* sBh = sAl + 256 * LDS_;                            // 64*LDS_
    __nv_bfloat16* sBl = sBh + 64 * LDS_;

    const int zb = blockIdx.z;
    const int n0 = blockIdx.x * 64;
    const float* Qb = Q + (size_t)zb * D_ * LQ;
    const float* Tb = T + (size_t)zb * LQ * D_;
    const float* Eb = E + (size_t)zb * LC * LQ;
    const float* qm = qmask + zb * LQ;
    const float* qc = qcinv + zb * LQ;

    const int tid = threadIdx.x, wid = tid >> 5, lane = tid & 31;
    const int wm = (wid >> 1) * 64, wn = (wid & 1) * 32;

    float acc[4][4][4];
#pragma unroll
    for (int i = 0; i < 4; i++)
#pragma unroll
        for (int j = 0; j < 4; j++)
#pragma unroll
            for (int e = 0; e < 4; e++) acc[i][j][e] = 0.f;

    float4 ra[8], rb[2];

    auto ldgA = [&](int kk) {
#pragma unroll
        for (int i = 0; i < 4; i++) {                 // Q half, rows 0..127, K-fast
            int v = i * 256 + tid;
            int row = v >> 3, c4 = v & 7;
            float4 x = *reinterpret_cast<const float4*>(Qb + (size_t)row * LQ + kk + c4 * 4);
            float4 s = *reinterpret_cast<const float4*>(qm + kk + c4 * 4);
            x.x *= s.x; x.y *= s.y; x.z *= s.z; x.w *= s.w;
            ra[i] = x;
        }
#pragma unroll
        for (int i = 0; i < 4; i++) {                 // T half, rows 128..255, K-slow
            int v = i * 256 + tid;
            int mn = v & 127, krb = v >> 7;
            const float* p = Tb + (size_t)(kk + krb * 4) * D_ + mn;
            const float* s = qc + kk + krb * 4;
            float4 x;
            x.x = p[0] * s[0]; x.y = p[D_] * s[1];
            x.z = p[2 * D_] * s[2]; x.w = p[3 * D_] * s[3];
            ra[4 + i] = x;
        }
    };
    auto ldgB = [&](int kk) {
#pragma unroll
        for (int i = 0; i < 2; i++) {                 // E tile, 64 rows (l), K-fast
            int v = i * 256 + tid;
            int row = v >> 3, c4 = v & 7;
            rb[i] = *reinterpret_cast<const float4*>(Eb + (size_t)(n0 + row) * LQ + kk + c4 * 4);
        }
    };
    auto sts = [&]() {
#pragma unroll
        for (int i = 0; i < 4; i++) {
            int v = i * 256 + tid;
            int row = v >> 3, c4 = v & 7;
            uint2 uh, ul; cvt4(ra[i], uh, ul);
            int off = row * LDS_ + c4 * 4;
            *reinterpret_cast<uint2*>(sAh + off) = uh;
            *reinterpret_cast<uint2*>(sAl + off) = ul;
        }
#pragma unroll
        for (int i = 0; i < 4; i++) {
            int v = i * 256 + tid;
            int mn = v & 127, krb = v >> 7;
            uint2 uh, ul; cvt4(ra[4 + i], uh, ul);
            int off = (128 + mn) * LDS_ + krb * 4;
            *reinterpret_cast<uint2*>(sAh + off) = uh;
            *reinterpret_cast<uint2*>(sAl + off) = ul;
        }
#pragma unroll
        for (int i = 0; i < 2; i++) {
            int v = i * 256 + tid;
            int row = v >> 3, c4 = v & 7;
            uint2 uh, ul; cvt4(rb[i], uh, ul);
            int off = row * LDS_ + c4 * 4;
            *reinterpret_cast<uint2*>(sBh + off) = uh;
            *reinterpret_cast<uint2*>(sBl + off) = ul;
        }
    };

    const uint32_t bAh = smem_u32(sAh), bAl = smem_u32(sAl);
    const uint32_t bBh = smem_u32(sBh), bBl = smem_u32(sBl);

    const int nch = LQ >> 5;   // 8
    ldgA(0); ldgB(0);
    for (int ch = 0; ch < nch; ch++) {
        sts();
        __syncthreads();
        if (ch + 1 < nch) { ldgA((ch + 1) << 5); ldgB((ch + 1) << 5); }
#pragma unroll
        for (int ks = 0; ks < 2; ks++) {
            uint32_t afh[4][4], afl[4][4];
#pragma unroll
            for (int mt = 0; mt < 4; mt++) {
                uint32_t aoff = (uint32_t)((wm + mt * 16 + (lane & 15)) * LDS_
                                           + ks * 16 + ((lane >> 4) << 3)) * 2u;
                LDSM_X4(afh[mt], bAh + aoff);
                LDSM_X4(afl[mt], bAl + aoff);
            }
            uint32_t bfh[2][4], bfl[2][4];
#pragma unroll
            for (int nt = 0; nt < 2; nt++) {
                uint32_t boff = (uint32_t)((wn + nt * 16 + ((lane >> 4) << 3) + (lane & 7)) * LDS_
                                           + ks * 16 + (((lane >> 3) & 1) << 3)) * 2u;
                LDSM_X4(bfh[nt], bBh + boff);
                LDSM_X4(bfl[nt], bBl + boff);
            }
#pragma unroll
            for (int mt = 0; mt < 4; mt++)
#pragma unroll
                for (int nt = 0; nt < 2; nt++)
#pragma unroll
                    for (int h = 0; h < 2; h++) {
                        float* c = acc[mt][nt * 2 + h];
                        MMA_BF16(c, afh[mt], bfh[nt][2 * h], bfh[nt][2 * h + 1]);
                        MMA_BF16(c, afh[mt], bfl[nt][2 * h], bfl[nt][2 * h + 1]);
                        MMA_BF16(c, afl[mt], bfh[nt][2 * h], bfh[nt][2 * h + 1]);
                    }
        }
        __syncthreads();
    }

    // epilogue: rows < 128 => At (channels 0,1,2); rows >= 128 => Bv (channel 3)
    const float* Cb = C + (size_t)zb * D_ * LC;
    const float* rv = rinv + zb * LC;
    float* O = out + (size_t)zb * 4 * D_ * LC;
#pragma unroll
    for (int mt = 0; mt < 4; mt++) {
        int r0 = wm + mt * 16 + (lane >> 2);
        int r1 = r0 + 8;
#pragma unroll
        for (int nt = 0; nt < 4; nt++) {
            int col = n0 + wn + nt * 8 + (lane & 3) * 2;
            float c0 = rv[col], c1v = rv[col + 1];
            float2 v0, v1;
            v0.x = acc[mt][nt][0] * c0; v0.y = acc[mt][nt][1] * c1v;
            v1.x = acc[mt][nt][2] * c0; v1.y = acc[mt][nt][3] * c1v;
            if (wm < 128) {
                int d0 = r0, d1 = r1;
                float2 cc0 = *reinterpret_cast<const float2*>(Cb + (size_t)d0 * LC + col);
                float2 cc1 = *reinterpret_cast<const float2*>(Cb + (size_t)d1 * LC + col);
                *reinterpret_cast<float2*>(O + (size_t)d0 * LC + col) = cc0;
                *reinterpret_cast<float2*>(O + (size_t)d1 * LC + col) = cc1;
                *reinterpret_cast<float2*>(O + (size_t)(D_ + d0) * LC + col) = v0;
                *reinterpret_cast<float2*>(O + (size_t)(D_ + d1) * LC + col) = v1;
                float2 m0v, m1v;
                m0v.x = cc0.x * v0.x; m0v.y = cc0.y * v0.y;
                m1v.x = cc1.x * v1.x; m1v.y = cc1.y * v1.y;
                *reinterpret_cast<float2*>(O + (size_t)(2 * D_ + d0) * LC + col) = m0v;
                *reinterpret_cast<float2*>(O + (size_t)(2 * D_ + d1) * LC + col) = m1v;
            } else {
                int d0 = r0 - 128, d1 = r1 - 128;
                float2 cc0 = *reinterpret_cast<const float2*>(Cb + (size_t)d0 * LC + col);
                float2 cc1 = *reinterpret_cast<const float2*>(Cb + (size_t)d1 * LC + col);
                float2 b0v, b1v;
                b0v.x = cc0.x * v0.x; b0v.y = cc0.y * v0.y;
                b1v.x = cc1.x * v1.x; b1v.y = cc1.y * v1.y;
                *reinterpret_cast<float2*>(O + (size_t)(3 * D_ + d0) * LC + col) = b0v;
                *reinterpret_cast<float2*>(O + (size_t)(3 * D_ + d1) * LC + col) = b1v;
            }
        }
    }
}

// ---------------- K1: bias vectors c1[l] = Ct.w1, q2[m] = Qt.w2 ----------------
__global__ void k_bias(const float* __restrict__ C, const float* __restrict__ Q,
                       const float* __restrict__ w) {
    int b = blockIdx.y, seg = blockIdx.x, t = threadIdx.x;
    if (seg < 4) {
        int l = seg * 256 + t;
        const float* Cb = C + (size_t)b * D_ * LC;
        float acc = 0.f;
#pragma unroll 8
        for (int d = 0; d < D_; d++) acc += Cb[(size_t)d * LC + l] * __ldg(w + d);
        g_c1[b * LC + l] = acc;
    } else {
        int m = t;
        const float* Qb = Q + (size_t)b * D_ * LQ;
        float acc = 0.f;
#pragma unroll 8
        for (int d = 0; d < D_; d++) acc += Qb[(size_t)d * LQ + m] * __ldg(w + D_ + d);
        g_q2[b * LQ + m] = acc;
    }
}

// ---------------- sums: rinv[l] = 1/sum_m E*qm, col partials for cinv ----------------
__global__ __launch_bounds__(256) void k_sums(const float* __restrict__ qmask,
                                              const float* __restrict__ cmask) {
    int b = blockIdx.y, rc = blockIdx.x;
    int w = threadIdx.x >> 5, lane = threadIdx.x & 31;
    __shared__ float cp[8][256];
    float4 q0 = *reinterpret_cast<const float4*>(qmask + b * LQ + lane * 4);
    float4 q1 = *reinterpret_cast<const float4*>(qmask + b * LQ + 128 + lane * 4);
    float col[8] = {0.f, 0.f, 0.f, 0.f, 0.f, 0.f, 0.f, 0.f};
#pragma unroll 4
    for (int rr = 0; rr < 16; rr++) {
        int l = rc * 128 + w * 16 + rr;
        const float* Er = g_E + ((size_t)b * LC + l) * LQ;
        float4 e0 = *reinterpret_cast<const float4*>(Er + lane * 4);
        float4 e1 = *reinterpret_cast<const float4*>(Er + 128 + lane * 4);
        float cm = cmask[b * LC + l];
        col[0] += e0.x * cm; col[1] += e0.y * cm; col[2] += e0.z * cm; col[3] += e0.w * cm;
        col[4] += e1.x * cm; col[5] += e1.y * cm; col[6] += e1.z * cm; col[7] += e1.w * cm;
        float s = e0.x * q0.x + e0.y * q0.y + e0.z * q0.z + e0.w * q0.w
                + e1.x * q1.x + e1.y * q1.y + e1.z * q1.z + e1.w * q1.w;
#pragma unroll
        for (int o = 16; o; o >>= 1) s += __shfl_xor_sync(0xffffffffu, s, o);
        if (lane == 0) g_rinv[b * LC + l] = 1.f / s;
    }
#pragma unroll
    for (int j = 0; j < 4; j++) {
        cp[w][lane * 4 + j] = col[j];
        cp[w][128 + lane * 4 + j] = col[4 + j];
    }
    __syncthreads();
    int m = threadIdx.x;
    float c = cp[0][m] + cp[1][m] + cp[2][m] + cp[3][m]
            + cp[4][m] + cp[5][m] + cp[6][m] + cp[7][m];
    g_cpart[(b * 8 + rc) * 256 + m] = c;
}

__global__ void k_colfin(const float* __restrict__ qmask) {
    int b = blockIdx.x, m = threadIdx.x;
    const float* p = g_cpart + b * 8 * 256 + m;
    float c = p[0] + p[256] + p[512] + p[768] + p[1024] + p[1280] + p[1536] + p[1792];
    g_qcinv[b * LQ + m] = qmask[b * LQ + m] / c;
}

// ---------------- launch ----------------
extern "C" void kernel_launch(void* const* d_in, const int* in_sizes, int n_in,
                              void* d_out, int out_size) {
    const float* C     = (const float*)d_in[0];
    const float* Q     = (const float*)d_in[1];
    const float* cmask = (const float*)d_in[2];
    const float* qmask = (const float*)d_in[3];
    const float* w     = (const float*)d_in[4];
    float* out = (float*)d_out;

    float *pE, *pT, *pc1, *pq2, *prv, *pqc;
    cudaGetSymbolAddress((void**)&pE,   g_E);
    cudaGetSymbolAddress((void**)&pT,   g_T);
    cudaGetSymbolAddress((void**)&pc1,  g_c1);
    cudaGetSymbolAddress((void**)&pq2,  g_q2);
    cudaGetSymbolAddress((void**)&prv,  g_rinv);
    cudaGetSymbolAddress((void**)&pqc,  g_qcinv);

    static int g24_smem_set = 0;
    const int G24_SMEM = (256 + 256 + 64 + 64) * LDS_ * 2;   // 51200 B
    if (!g24_smem_set) {
        cudaFuncSetAttribute(g24, cudaFuncAttributeMaxDynamicSharedMemorySize, G24_SMEM);
        g24_smem_set = 1;
    }

    // 1: bias vectors
    k_bias<<<dim3(5, B_), 256>>>(C, Q, w);

    // 2: G1  E = exp((C*w3)^T Q + c1 + q2)   [m=l (8 tiles), n=m' (2), K=D]
    tgemm<true, true, true, false, 1><<<dim3(2, 8, B_), 256>>>(
        C, LC, (long)D_ * LC,  Q, LQ, (long)D_ * LQ,
        pE, LQ, (long)LC * LQ,  D_,
        w + 2 * D_, 0,  nullptr, 0,  pc1, pq2);

    // 3: sums -> rinv, col partials
    k_sums<<<dim3(8, B_), 256>>>(qmask, cmask);

    // 4 (profiled): G3  T_raw[m'][d] = sum_l E(l,m')*cm(l)*C(d,l)   [m=m' (2), n=d (1), K=Lc]
    tgemm<true, false, false, true, 0><<<dim3(1, 2, B_), 256>>>(
        pE, LQ, (long)LC * LQ,  C, LC, (long)D_ * LC,
        pT, D_, (long)LQ * D_,  LC,
        nullptr, 0,  cmask, LC,  nullptr, nullptr);

    // 5: qcinv[m'] = qm(m') / colsum(m')
    k_colfin<<<B_, 256>>>(qmask);

    // 6: fused G2+G4 + output assembly
    g24<<<dim3(LC / 64, 1, B_), 256, G24_SMEM>>>(
        Q, pT, pE, C, qmask, pqc, prv, out);
}